// round 1
// baseline (speedup 1.0000x reference)
#include <cuda_runtime.h>
#include <math.h>

// Problem constants
#define Bn  16
#define ICn 128
#define OCn 128
#define SDn 512
#define Hn  128
#define Wn  128

// 1/sqrt(IC*K*K) = 1/sqrt(1152), 1/sqrt(SD) = 1/sqrt(512)
#define CONV_SCALE 0.029462782549439476f
#define LIN_SCALE  0.044194173824159216f
#define EPSV       1e-8f

// Scratch (device globals — no allocation allowed in kernel_launch)
__device__ float g_s[Bn * ICn];          // modulation s[b][ic]
__device__ float g_q[OCn * ICn];         // q[oc][ic] = sum_t w^2
__device__ float g_demod[Bn * OCn];      // demod[b][oc]
__device__ float g_wf[Bn * ICn * 9 * OCn]; // folded weights, layout [b][ic][t][oc] (9.4 MB)

// ---------------------------------------------------------------------------
// Stage A1: s[b][ic] = dot(style[b], mod_w[ic]) * lin_scale + mod_b[ic]
// grid(16), block(128)
// ---------------------------------------------------------------------------
__global__ void k_mod(const float* __restrict__ style,
                      const float* __restrict__ mod_w,
                      const float* __restrict__ mod_b) {
    int b  = blockIdx.x;
    int ic = threadIdx.x;
    const float4* st = (const float4*)(style + b * SDn);
    const float4* mw = (const float4*)(mod_w + ic * SDn);
    float acc = 0.f;
#pragma unroll 4
    for (int d = 0; d < SDn / 4; d++) {
        float4 a = st[d], w = mw[d];
        acc += a.x * w.x + a.y * w.y + a.z * w.z + a.w * w.w;
    }
    g_s[b * ICn + ic] = acc * LIN_SCALE + mod_b[ic];
}

// ---------------------------------------------------------------------------
// Stage A2a: q[oc][ic] = sum over 9 taps of weight^2
// grid(64), block(256)  -> 16384 threads
// ---------------------------------------------------------------------------
__global__ void k_q(const float* __restrict__ weight) {
    int i = blockIdx.x * 256 + threadIdx.x;  // i = oc*128 + ic
    const float* w = weight + i * 9;
    float acc = 0.f;
#pragma unroll
    for (int t = 0; t < 9; t++) acc += w[t] * w[t];
    g_q[i] = acc;
}

// ---------------------------------------------------------------------------
// Stage A2b: demod[b][oc] = 1/sqrt(cs^2 * sum_ic s^2 * q + eps)
// grid(16), block(128)
// ---------------------------------------------------------------------------
__global__ void k_demod() {
    int b = blockIdx.x;
    int oc = threadIdx.x;
    float acc = 0.f;
#pragma unroll 4
    for (int ic = 0; ic < ICn; ic++) {
        float s = g_s[b * ICn + ic];
        acc += s * s * g_q[oc * ICn + ic];
    }
    g_demod[b * OCn + oc] = 1.0f / sqrtf(CONV_SCALE * CONV_SCALE * acc + EPSV);
}

// ---------------------------------------------------------------------------
// Stage A3: folded weights Wf[b][ic][t][oc] = cs * w[oc][ic][t] * s[b][ic] * demod[b][oc]
// grid(9216), block(256)  -> 2359296 threads
// ---------------------------------------------------------------------------
__global__ void k_wf(const float* __restrict__ weight) {
    int idx = blockIdx.x * 256 + threadIdx.x;
    int oc = idx & 127;
    int r  = idx >> 7;
    int t  = r % 9;  r /= 9;
    int ic = r & 127;
    int b  = r >> 7;
    g_wf[idx] = CONV_SCALE * weight[(oc * ICn + ic) * 9 + t]
              * g_s[b * ICn + ic] * g_demod[b * OCn + oc];
}

// ---------------------------------------------------------------------------
// Main conv: direct 3x3, SAME padding.
// Per CTA: one sample b, 64 output channels, 8x32 output tile.
// IC chunked by 8 through shared memory.
// Thread (256/CTA): 8 OC x 8 pixels accumulators.
//   tid -> pg = tid>>3 (pixel group 0..31), og = tid&7 (oc group 0..7)
//   pg  -> prow = pg>>2 (0..7), pcol = (pg&3)*8
// ---------------------------------------------------------------------------
#define CI     8
#define TILE_H 8
#define TILE_W 32
#define OCB    64

__global__ __launch_bounds__(256, 2)
void k_conv(const float* __restrict__ content, float* __restrict__ out) {
    const int b     = blockIdx.z;
    const int ocblk = blockIdx.y;                 // 0..1
    const int tile  = blockIdx.x;                 // 0..63
    const int ty    = tile >> 2;                  // 0..15
    const int tx    = tile & 3;                   // 0..3
    const int y0    = ty * TILE_H;
    const int x0    = tx * TILE_W;

    const int tid  = threadIdx.x;
    const int pg   = tid >> 3;
    const int og   = tid & 7;
    const int prow = pg >> 2;
    const int pcol = (pg & 3) * 8;

    __shared__ float sIn[CI][TILE_H + 2][TILE_W + 2];   // 8*10*34*4 = 10880 B
    __shared__ float sW[CI][9][OCB];                    // 8*9*64*4  = 18432 B

    float acc[8][8];
#pragma unroll
    for (int j = 0; j < 8; j++)
#pragma unroll
        for (int p = 0; p < 8; p++) acc[j][p] = 0.f;

    for (int c0 = 0; c0 < ICn; c0 += CI) {
        // ---- load input halo tile (zero-padded at borders) ----
        const int IN_ELEMS = CI * (TILE_H + 2) * (TILE_W + 2);  // 2720
        for (int e = tid; e < IN_ELEMS; e += 256) {
            int ci  = e / ((TILE_H + 2) * (TILE_W + 2));
            int rem = e % ((TILE_H + 2) * (TILE_W + 2));
            int r   = rem / (TILE_W + 2);
            int cc  = rem % (TILE_W + 2);
            int gy = y0 - 1 + r;
            int gx = x0 - 1 + cc;
            float v = 0.f;
            if (gy >= 0 && gy < Hn && gx >= 0 && gx < Wn)
                v = content[((b * ICn + c0 + ci) * Hn + gy) * Wn + gx];
            sIn[ci][r][cc] = v;
        }
        // ---- load folded weights (coalesced: oc contiguous) ----
        const int W_ELEMS = CI * 9 * OCB;  // 4608
        for (int e = tid; e < W_ELEMS; e += 256) {
            int ci  = e / (9 * OCB);
            int rem = e % (9 * OCB);
            int t   = rem / OCB;
            int oc  = rem % OCB;
            sW[ci][t][oc] = g_wf[((b * ICn + c0 + ci) * 9 + t) * OCn + ocblk * OCB + oc];
        }
        __syncthreads();

#pragma unroll 1
        for (int ci = 0; ci < CI; ci++) {
#pragma unroll
            for (int ky = 0; ky < 3; ky++) {
                float xr[10];
#pragma unroll
                for (int c = 0; c < 10; c++)
                    xr[c] = sIn[ci][prow + ky][pcol + c];
#pragma unroll
                for (int kx = 0; kx < 3; kx++) {
                    float4 w0 = *(const float4*)&sW[ci][ky * 3 + kx][og * 8];
                    float4 w1 = *(const float4*)&sW[ci][ky * 3 + kx][og * 8 + 4];
                    float wv[8] = {w0.x, w0.y, w0.z, w0.w, w1.x, w1.y, w1.z, w1.w};
#pragma unroll
                    for (int j = 0; j < 8; j++)
#pragma unroll
                        for (int p = 0; p < 8; p++)
                            acc[j][p] += wv[j] * xr[p + kx];
                }
            }
        }
        __syncthreads();
    }

    // ---- write 8 OC x 8 px per thread, float4 pairs ----
#pragma unroll
    for (int j = 0; j < 8; j++) {
        int oc = ocblk * OCB + og * 8 + j;
        float* o = out + ((size_t)(b * OCn + oc) * Hn + (y0 + prow)) * Wn + x0 + pcol;
        float4 v0 = make_float4(acc[j][0], acc[j][1], acc[j][2], acc[j][3]);
        float4 v1 = make_float4(acc[j][4], acc[j][5], acc[j][6], acc[j][7]);
        *(float4*)o       = v0;
        *(float4*)(o + 4) = v1;
    }
}

// ---------------------------------------------------------------------------
// Inputs (metadata order): content, style, weight, mod_w, mod_b. Output fp32.
// ---------------------------------------------------------------------------
extern "C" void kernel_launch(void* const* d_in, const int* in_sizes, int n_in,
                              void* d_out, int out_size) {
    const float* content = (const float*)d_in[0];
    const float* style   = (const float*)d_in[1];
    const float* weight  = (const float*)d_in[2];
    const float* mod_w   = (const float*)d_in[3];
    const float* mod_b   = (const float*)d_in[4];
    float* out = (float*)d_out;

    k_mod  <<<Bn, ICn>>>(style, mod_w, mod_b);
    k_q    <<<(OCn * ICn) / 256, 256>>>(weight);
    k_demod<<<Bn, OCn>>>();
    k_wf   <<<(Bn * ICn * 9 * OCn) / 256, 256>>>(weight);
    k_conv <<<dim3((Hn / TILE_H) * (Wn / TILE_W), OCn / OCB, Bn), 256>>>(content, out);
}

// round 3
// speedup vs baseline: 1.2367x; 1.2367x over previous
#include <cuda_runtime.h>
#include <math.h>

// Problem constants
#define Bn  16
#define ICn 128
#define OCn 128
#define SDn 512
#define Hn  128
#define Wn  128

// 1/sqrt(IC*K*K) = 1/sqrt(1152), 1/sqrt(SD) = 1/sqrt(512)
#define CONV_SCALE 0.029462782549439476f
#define LIN_SCALE  0.044194173824159216f
#define EPSV       1e-8f

typedef unsigned long long u64;

// Scratch (device globals — allocation is forbidden in kernel_launch)
__device__ float g_s[Bn * ICn];            // modulation s[b][ic]
__device__ float g_q[OCn * ICn];           // q[oc][ic] = sum_t w^2
__device__ float g_wf[Bn * ICn * 9 * OCn]; // folded weights [b][ic][t][oc] (9.4 MB)

// ---- f32x2 packed helpers (Blackwell sm_100a) ------------------------------
__device__ __forceinline__ u64 pk2(float lo, float hi) {
    u64 r; asm("mov.b64 %0, {%1, %2};" : "=l"(r) : "f"(lo), "f"(hi)); return r;
}
__device__ __forceinline__ void upk2(u64 v, float& lo, float& hi) {
    asm("mov.b64 {%0, %1}, %2;" : "=f"(lo), "=f"(hi) : "l"(v));
}
__device__ __forceinline__ u64 ffma2(u64 a, u64 b, u64 c) {
    u64 r; asm("fma.rn.f32x2 %0, %1, %2, %3;" : "=l"(r) : "l"(a), "l"(b), "l"(c));
    return r;
}

// ---------------------------------------------------------------------------
// Prolog 1 (fused): blocks 0..15   -> s[b][ic]  (b = blockIdx, ic = tid)
//                   blocks 16..143 -> q[i]      (i = (blockIdx-16)*128 + tid)
// ---------------------------------------------------------------------------
__global__ void k_pre(const float* __restrict__ style,
                      const float* __restrict__ mod_w,
                      const float* __restrict__ mod_b,
                      const float* __restrict__ weight) {
    if (blockIdx.x < 16) {
        int b  = blockIdx.x;
        int ic = threadIdx.x;
        const float4* st = (const float4*)(style + b * SDn);
        const float4* mw = (const float4*)(mod_w + ic * SDn);
        float acc = 0.f;
#pragma unroll 4
        for (int d = 0; d < SDn / 4; d++) {
            float4 a = st[d], w = mw[d];
            acc += a.x * w.x + a.y * w.y + a.z * w.z + a.w * w.w;
        }
        g_s[b * ICn + ic] = acc * LIN_SCALE + mod_b[ic];
    } else {
        int i = (blockIdx.x - 16) * 128 + threadIdx.x;  // i = oc*128+ic
        const float* w = weight + i * 9;
        float acc = 0.f;
#pragma unroll
        for (int t = 0; t < 9; t++) acc += w[t] * w[t];
        g_q[i] = acc;
    }
}

// ---------------------------------------------------------------------------
// Prolog 2 (fused demod + weight fold): grid(16)=b, block(256)
//   phase 1: demod[oc] = 1/sqrt(cs^2 * sum_ic s^2 q + eps)  in smem
//   phase 2: Wf[b][ic][t][oc] = cs * w * s[ic] * demod[oc]
// ---------------------------------------------------------------------------
__global__ void k_wf(const float* __restrict__ weight) {
    int b   = blockIdx.x;
    int tid = threadIdx.x;
    __shared__ float s_sm[ICn];
    __shared__ float dm[OCn];
    if (tid < ICn) s_sm[tid] = g_s[b * ICn + tid];
    __syncthreads();
    if (tid < OCn) {
        float acc = 0.f;
#pragma unroll 4
        for (int ic = 0; ic < ICn; ic++) {
            float s = s_sm[ic];
            acc += s * s * g_q[tid * ICn + ic];
        }
        dm[tid] = 1.0f / sqrtf(CONV_SCALE * CONV_SCALE * acc + EPSV);
    }
    __syncthreads();
    const int TOT = ICn * 9 * OCn;  // 147456
    for (int e = tid; e < TOT; e += 256) {
        int oc = e & 127;
        int r  = e >> 7;
        int t  = r % 9;
        int ic = r / 9;
        g_wf[b * TOT + e] = CONV_SCALE * weight[(oc * ICn + ic) * 9 + t]
                          * s_sm[ic] * dm[oc];
    }
}

// ---------------------------------------------------------------------------
// Main conv: direct 3x3, SAME padding, f32x2 packed FMA (OC paired).
// Per CTA: one sample b, 64 output channels, 8x32 output tile, IC chunked by 8.
// Thread: 8 OC (as 4 f32x2 pairs) x 8 pixels.
//   tid -> pg = tid>>3 (pixel group), og = tid&7 (oc group)
//   pg  -> prow = pg>>2, pcol = (pg&3)*8
// ---------------------------------------------------------------------------
#define CI     8
#define TILE_H 8
#define TILE_W 32
#define OCB    64

__global__ __launch_bounds__(256, 2)
void k_conv(const float* __restrict__ content, float* __restrict__ out) {
    const int b     = blockIdx.z;
    const int ocblk = blockIdx.y;                 // 0..1
    const int tile  = blockIdx.x;                 // 0..63
    const int ty    = tile >> 2;                  // 0..15
    const int tx    = tile & 3;                   // 0..3
    const int y0    = ty * TILE_H;
    const int x0    = tx * TILE_W;

    const int tid  = threadIdx.x;
    const int pg   = tid >> 3;
    const int og   = tid & 7;
    const int prow = pg >> 2;
    const int pcol = (pg & 3) * 8;

    __shared__ float sIn[CI][TILE_H + 2][TILE_W + 2];   // 10880 B
    __shared__ __align__(16) float sW[CI][9][OCB];      // 18432 B

    u64 acc[4][8];   // [oc-pair][pixel]; pair = (oc 2j, oc 2j+1)
#pragma unroll
    for (int j = 0; j < 4; j++)
#pragma unroll
        for (int p = 0; p < 8; p++) acc[j][p] = 0ull;

    for (int c0 = 0; c0 < ICn; c0 += CI) {
        // ---- load input halo tile (zero-padded at borders) ----
        const int IN_ELEMS = CI * (TILE_H + 2) * (TILE_W + 2);  // 2720
        for (int e = tid; e < IN_ELEMS; e += 256) {
            int ci  = e / ((TILE_H + 2) * (TILE_W + 2));
            int rem = e % ((TILE_H + 2) * (TILE_W + 2));
            int r   = rem / (TILE_W + 2);
            int cc  = rem % (TILE_W + 2);
            int gy = y0 - 1 + r;
            int gx = x0 - 1 + cc;
            float v = 0.f;
            if (gy >= 0 && gy < Hn && gx >= 0 && gx < Wn)
                v = content[((b * ICn + c0 + ci) * Hn + gy) * Wn + gx];
            sIn[ci][r][cc] = v;
        }
        // ---- load folded weights (coalesced: oc contiguous) ----
        const int W_ELEMS = CI * 9 * OCB;  // 4608
        for (int e = tid; e < W_ELEMS; e += 256) {
            int ci  = e / (9 * OCB);
            int rem = e % (9 * OCB);
            int t   = rem / OCB;
            int oc  = rem % OCB;
            sW[ci][t][oc] = g_wf[((b * ICn + c0 + ci) * 9 + t) * OCn + ocblk * OCB + oc];
        }
        __syncthreads();

#pragma unroll 1
        for (int ci = 0; ci < CI; ci++) {
#pragma unroll
            for (int ky = 0; ky < 3; ky++) {
                // broadcast pairs (x, x) for the 10-wide row window
                u64 xb[10];
#pragma unroll
                for (int c = 0; c < 10; c++) {
                    float v = sIn[ci][prow + ky][pcol + c];
                    xb[c] = pk2(v, v);
                }
#pragma unroll
                for (int kx = 0; kx < 3; kx++) {
                    const u64* wp = (const u64*)&sW[ci][ky * 3 + kx][og * 8];
                    u64 w0 = wp[0], w1 = wp[1], w2 = wp[2], w3 = wp[3];
#pragma unroll
                    for (int p = 0; p < 8; p++) {
                        u64 x = xb[p + kx];
                        acc[0][p] = ffma2(w0, x, acc[0][p]);
                        acc[1][p] = ffma2(w1, x, acc[1][p]);
                        acc[2][p] = ffma2(w2, x, acc[2][p]);
                        acc[3][p] = ffma2(w3, x, acc[3][p]);
                    }
                }
            }
        }
        __syncthreads();
    }

    // ---- write out: each oc-pair gives two oc rows of 8 pixels ----
#pragma unroll
    for (int j = 0; j < 4; j++) {
        float lo[8], hi[8];
#pragma unroll
        for (int p = 0; p < 8; p++) upk2(acc[j][p], lo[p], hi[p]);
        int oc0 = ocblk * OCB + og * 8 + 2 * j;
        float* o0 = out + ((size_t)(b * OCn + oc0)     * Hn + (y0 + prow)) * Wn + x0 + pcol;
        float* o1 = out + ((size_t)(b * OCn + oc0 + 1) * Hn + (y0 + prow)) * Wn + x0 + pcol;
        *(float4*)o0       = make_float4(lo[0], lo[1], lo[2], lo[3]);
        *(float4*)(o0 + 4) = make_float4(lo[4], lo[5], lo[6], lo[7]);
        *(float4*)o1       = make_float4(hi[0], hi[1], hi[2], hi[3]);
        *(float4*)(o1 + 4) = make_float4(hi[4], hi[5], hi[6], hi[7]);
    }
}

// ---------------------------------------------------------------------------
// Inputs (metadata order): content, style, weight, mod_w, mod_b. Output fp32.
// ---------------------------------------------------------------------------
extern "C" void kernel_launch(void* const* d_in, const int* in_sizes, int n_in,
                              void* d_out, int out_size) {
    const float* content = (const float*)d_in[0];
    const float* style   = (const float*)d_in[1];
    const float* weight  = (const float*)d_in[2];
    const float* mod_w   = (const float*)d_in[3];
    const float* mod_b   = (const float*)d_in[4];
    float* out = (float*)d_out;

    k_pre <<<144, 128>>>(style, mod_w, mod_b, weight);
    k_wf  <<<Bn, 256>>>(weight);
    k_conv<<<dim3((Hn / TILE_H) * (Wn / TILE_W), OCn / OCB, Bn), 256>>>(content, out);
}

// round 4
// speedup vs baseline: 1.2386x; 1.0016x over previous
#include <cuda_runtime.h>
#include <math.h>

// Problem constants
#define Bn  16
#define ICn 128
#define OCn 128
#define SDn 512
#define Hn  128
#define Wn  128

// 1/sqrt(IC*K*K) = 1/sqrt(1152), 1/sqrt(SD) = 1/sqrt(512)
#define CONV_SCALE 0.029462782549439476f
#define LIN_SCALE  0.044194173824159216f
#define EPSV       1e-8f

typedef unsigned long long u64;

// Scratch (device globals — allocation is forbidden in kernel_launch)
__device__ float g_s[Bn * ICn];            // modulation s[b][ic]
__device__ float g_q[OCn * ICn];           // q[oc][ic] = sum_t w^2
__device__ float g_wf[Bn * ICn * 9 * OCn]; // folded weights [b][ic][t][oc] (9.4 MB)

// ---- f32x2 packed helpers (Blackwell sm_100a) ------------------------------
__device__ __forceinline__ u64 pk2(float lo, float hi) {
    u64 r; asm("mov.b64 %0, {%1, %2};" : "=l"(r) : "f"(lo), "f"(hi)); return r;
}
__device__ __forceinline__ void upk2(u64 v, float& lo, float& hi) {
    asm("mov.b64 {%0, %1}, %2;" : "=f"(lo), "=f"(hi) : "l"(v));
}
__device__ __forceinline__ u64 ffma2(u64 a, u64 b, u64 c) {
    u64 r; asm("fma.rn.f32x2 %0, %1, %2, %3;" : "=l"(r) : "l"(a), "l"(b), "l"(c));
    return r;
}

// ---------------------------------------------------------------------------
// Prolog 1 (fused): blocks 0..15   -> s[b][ic]  (b = blockIdx, ic = tid)
//                   blocks 16..143 -> q[i]      (i = (blockIdx-16)*128 + tid)
// ---------------------------------------------------------------------------
__global__ void k_pre(const float* __restrict__ style,
                      const float* __restrict__ mod_w,
                      const float* __restrict__ mod_b,
                      const float* __restrict__ weight) {
    if (blockIdx.x < 16) {
        int b  = blockIdx.x;
        int ic = threadIdx.x;
        const float4* st = (const float4*)(style + b * SDn);
        const float4* mw = (const float4*)(mod_w + ic * SDn);
        float acc = 0.f;
#pragma unroll 4
        for (int d = 0; d < SDn / 4; d++) {
            float4 a = st[d], w = mw[d];
            acc += a.x * w.x + a.y * w.y + a.z * w.z + a.w * w.w;
        }
        g_s[b * ICn + ic] = acc * LIN_SCALE + mod_b[ic];
    } else {
        int i = (blockIdx.x - 16) * 128 + threadIdx.x;  // i = oc*128+ic
        const float* w = weight + i * 9;
        float acc = 0.f;
#pragma unroll
        for (int t = 0; t < 9; t++) acc += w[t] * w[t];
        g_q[i] = acc;
    }
}

// ---------------------------------------------------------------------------
// Prolog 2 (fused demod + weight fold): grid(16)=b, block(256)
//   phase 1: demod[oc] = 1/sqrt(cs^2 * sum_ic s^2 q + eps)  in smem
//   phase 2: Wf[b][ic][t][oc] = cs * w * s[ic] * demod[oc]
// ---------------------------------------------------------------------------
__global__ void k_wf(const float* __restrict__ weight) {
    int b   = blockIdx.x;
    int tid = threadIdx.x;
    __shared__ float s_sm[ICn];
    __shared__ float dm[OCn];
    if (tid < ICn) s_sm[tid] = g_s[b * ICn + tid];
    __syncthreads();
    if (tid < OCn) {
        float acc = 0.f;
#pragma unroll 4
        for (int ic = 0; ic < ICn; ic++) {
            float s = s_sm[ic];
            acc += s * s * g_q[tid * ICn + ic];
        }
        dm[tid] = 1.0f / sqrtf(CONV_SCALE * CONV_SCALE * acc + EPSV);
    }
    __syncthreads();
    const int TOT = ICn * 9 * OCn;  // 147456
    for (int e = tid; e < TOT; e += 256) {
        int oc = e & 127;
        int r  = e >> 7;
        int t  = r % 9;
        int ic = r / 9;
        g_wf[b * TOT + e] = CONV_SCALE * weight[(oc * ICn + ic) * 9 + t]
                          * s_sm[ic] * dm[oc];
    }
}

// ---------------------------------------------------------------------------
// Main conv: direct 3x3, SAME padding, f32x2 packed FMA (OC paired).
// Per CTA: one sample b, 64 output channels, 8x32 output tile, IC chunked by 8.
// Thread: 8 OC (as 4 f32x2 pairs) x 8 pixels.
//   tid -> pg = tid>>3 (pixel group), og = tid&7 (oc group)
//   pg  -> prow = pg>>2, pcol = (pg&3)*8
// ---------------------------------------------------------------------------
#define CI     8
#define TILE_H 8
#define TILE_W 32
#define OCB    64

__global__ __launch_bounds__(256, 2)
void k_conv(const float* __restrict__ content, float* __restrict__ out) {
    const int b     = blockIdx.z;
    const int ocblk = blockIdx.y;                 // 0..1
    const int tile  = blockIdx.x;                 // 0..63
    const int ty    = tile >> 2;                  // 0..15
    const int tx    = tile & 3;                   // 0..3
    const int y0    = ty * TILE_H;
    const int x0    = tx * TILE_W;

    const int tid  = threadIdx.x;
    const int pg   = tid >> 3;
    const int og   = tid & 7;
    const int prow = pg >> 2;
    const int pcol = (pg & 3) * 8;

    __shared__ float sIn[CI][TILE_H + 2][TILE_W + 2];   // 10880 B
    __shared__ __align__(16) float sW[CI][9][OCB];      // 18432 B

    u64 acc[4][8];   // [oc-pair][pixel]; pair = (oc 2j, oc 2j+1)
#pragma unroll
    for (int j = 0; j < 4; j++)
#pragma unroll
        for (int p = 0; p < 8; p++) acc[j][p] = 0ull;

    for (int c0 = 0; c0 < ICn; c0 += CI) {
        // ---- load input halo tile (zero-padded at borders) ----
        const int IN_ELEMS = CI * (TILE_H + 2) * (TILE_W + 2);  // 2720
        for (int e = tid; e < IN_ELEMS; e += 256) {
            int ci  = e / ((TILE_H + 2) * (TILE_W + 2));
            int rem = e % ((TILE_H + 2) * (TILE_W + 2));
            int r   = rem / (TILE_W + 2);
            int cc  = rem % (TILE_W + 2);
            int gy = y0 - 1 + r;
            int gx = x0 - 1 + cc;
            float v = 0.f;
            if (gy >= 0 && gy < Hn && gx >= 0 && gx < Wn)
                v = content[((b * ICn + c0 + ci) * Hn + gy) * Wn + gx];
            sIn[ci][r][cc] = v;
        }
        // ---- load folded weights (coalesced: oc contiguous) ----
        const int W_ELEMS = CI * 9 * OCB;  // 4608
        for (int e = tid; e < W_ELEMS; e += 256) {
            int ci  = e / (9 * OCB);
            int rem = e % (9 * OCB);
            int t   = rem / OCB;
            int oc  = rem % OCB;
            sW[ci][t][oc] = g_wf[((b * ICn + c0 + ci) * 9 + t) * OCn + ocblk * OCB + oc];
        }
        __syncthreads();

#pragma unroll 1
        for (int ci = 0; ci < CI; ci++) {
#pragma unroll
            for (int ky = 0; ky < 3; ky++) {
                // broadcast pairs (x, x) for the 10-wide row window
                u64 xb[10];
#pragma unroll
                for (int c = 0; c < 10; c++) {
                    float v = sIn[ci][prow + ky][pcol + c];
                    xb[c] = pk2(v, v);
                }
#pragma unroll
                for (int kx = 0; kx < 3; kx++) {
                    const u64* wp = (const u64*)&sW[ci][ky * 3 + kx][og * 8];
                    u64 w0 = wp[0], w1 = wp[1], w2 = wp[2], w3 = wp[3];
#pragma unroll
                    for (int p = 0; p < 8; p++) {
                        u64 x = xb[p + kx];
                        acc[0][p] = ffma2(w0, x, acc[0][p]);
                        acc[1][p] = ffma2(w1, x, acc[1][p]);
                        acc[2][p] = ffma2(w2, x, acc[2][p]);
                        acc[3][p] = ffma2(w3, x, acc[3][p]);
                    }
                }
            }
        }
        __syncthreads();
    }

    // ---- write out: each oc-pair gives two oc rows of 8 pixels ----
#pragma unroll
    for (int j = 0; j < 4; j++) {
        float lo[8], hi[8];
#pragma unroll
        for (int p = 0; p < 8; p++) upk2(acc[j][p], lo[p], hi[p]);
        int oc0 = ocblk * OCB + og * 8 + 2 * j;
        float* o0 = out + ((size_t)(b * OCn + oc0)     * Hn + (y0 + prow)) * Wn + x0 + pcol;
        float* o1 = out + ((size_t)(b * OCn + oc0 + 1) * Hn + (y0 + prow)) * Wn + x0 + pcol;
        *(float4*)o0       = make_float4(lo[0], lo[1], lo[2], lo[3]);
        *(float4*)(o0 + 4) = make_float4(lo[4], lo[5], lo[6], lo[7]);
        *(float4*)o1       = make_float4(hi[0], hi[1], hi[2], hi[3]);
        *(float4*)(o1 + 4) = make_float4(hi[4], hi[5], hi[6], hi[7]);
    }
}

// ---------------------------------------------------------------------------
// Inputs (metadata order): content, style, weight, mod_w, mod_b. Output fp32.
// ---------------------------------------------------------------------------
extern "C" void kernel_launch(void* const* d_in, const int* in_sizes, int n_in,
                              void* d_out, int out_size) {
    const float* content = (const float*)d_in[0];
    const float* style   = (const float*)d_in[1];
    const float* weight  = (const float*)d_in[2];
    const float* mod_w   = (const float*)d_in[3];
    const float* mod_b   = (const float*)d_in[4];
    float* out = (float*)d_out;

    k_pre <<<144, 128>>>(style, mod_w, mod_b, weight);
    k_wf  <<<Bn, 256>>>(weight);
    k_conv<<<dim3((Hn / TILE_H) * (Wn / TILE_W), OCn / OCB, Bn), 256>>>(content, out);
}